// round 11
// baseline (speedup 1.0000x reference)
#include <cuda_runtime.h>

// RoIAlign2D: features (4,256,96,96) f32, rois (1024,5) f32 -> out (1024,256,7,7) f32
// OUT_SIZE=7, SPATIAL_SCALE=0.0625, SAMPLE_NUM=2
//
// v4: Block = (roi, 16-channel group), smem ~33.8KB -> 6 blocks/SM (75% occ).
// Warp = two outputs per iteration via half-warps (lane = half*16 + channel):
// each tap LDS instruction fetches one 64B channel segment per half (2 outputs
// per instruction). Geometry hoisted to per-block float4 tables. Staging and
// transpose use stride-17 (conflict-free).

#define CC     256
#define HH     96
#define WW     96
#define SCALE  0.0625f
#define PATCH  21
#define CPAD   17
#define GROUP  16
#define HW     (HH * WW)

#define PATCH_ELEMS  (PATCH * PATCH * CPAD)   // 7497
#define OUTBUF_ELEMS (49 * CPAD)              // 833
#define TAB_FLOATS   (28 * 4)
#define SMEM_BYTES   ((TAB_FLOATS + PATCH_ELEMS + OUTBUF_ELEMS) * 4)  // 33768

__global__ __launch_bounds__(256) void roi_align_v4(
    const float* __restrict__ feat,
    const float* __restrict__ rois,
    float* __restrict__ out)
{
    extern __shared__ float smem[];
    float4* ytab   = (float4*)smem;            // [14]
    float4* xtab   = (float4*)smem + 14;       // [14]
    float*  patch  = smem + TAB_FLOATS;        // [PATCH][PATCH][CPAD]
    float*  outbuf = patch + PATCH_ELEMS;      // [49][CPAD]

    int blk = blockIdx.x;
    int k   = blk >> 4;              // roi index (16 channel groups per roi)
    int c0  = (blk & 15) * GROUP;

    const float* r = rois + k * 5;
    int   b  = (int)__ldg(r);
    float x1 = __ldg(r + 1) * SCALE;
    float y1 = __ldg(r + 2) * SCALE;
    float x2 = __ldg(r + 3) * SCALE;
    float y2 = __ldg(r + 4) * SCALE;

    float bw = fmaxf(x2 - x1, 1.0f) * (1.0f / 7.0f);
    float bh = fmaxf(y2 - y1, 1.0f) * (1.0f / 7.0f);

    // Patch bounds from first/last sample (monotone coords, clipped -> in-bounds).
    float xcf = fminf(fmaxf(x1 + bw * 0.25f, 0.0f), (float)(WW - 1));
    float ycf = fminf(fmaxf(y1 + bh * 0.25f, 0.0f), (float)(HH - 1));
    int x0 = (int)floorf(xcf);
    int y0 = (int)floorf(ycf);
    float xce = fminf(fmaxf(x1 + bw * 6.75f, 0.0f), (float)(WW - 1));
    float yce = fminf(fmaxf(y1 + bh * 6.75f, 0.0f), (float)(HH - 1));
    int xspan = min((int)floorf(xce) + 1, WW - 1) - x0 + 1;   // <= 21
    int yspan = min((int)floorf(yce) + 1, HH - 1) - y0 + 1;   // <= 21

    int tid  = threadIdx.x;
    int w    = tid >> 5;
    int lane = tid & 31;

    // ---- sample geometry tables (threads 0..27) ----
    if (tid < 28) {
        bool  isY   = tid < 14;
        int   s     = isY ? tid : tid - 14;
        float start = isY ? y1 : x1;
        float bsz   = isY ? bh : bw;
        int   size  = isY ? HH : WW;
        int   org   = isY ? y0 : x0;
        int   mul   = isY ? (PATCH * CPAD) : CPAD;

        float c  = start + bsz * (0.25f + 0.5f * (float)s);
        bool  v  = (c >= -1.0f) && (c <= (float)size);
        float cc = fminf(fmaxf(c, 0.0f), (float)(size - 1));
        float fl = floorf(cc);
        int   lo = (int)fl;
        int   hi = min(lo + 1, size - 1);
        float fr = cc - fl;
        float4 e;
        e.x = __int_as_float((lo - org) * mul);
        e.y = __int_as_float((hi - org) * mul);
        e.z = v ? (1.0f - fr) : 0.0f;
        e.w = v ? fr : 0.0f;
        if (isY) ytab[s] = e; else xtab[s] = e;
    }

    // ---- stage patch: warp-per-row, lane = x, 16-channel inner loop ----
    const float* fbase = feat + (size_t)(b * CC + c0) * HW;
    for (int y = w; y < yspan; y += 8) {
        if (lane < xspan) {
            const float* g = fbase + (y0 + y) * WW + x0 + lane;
            float*       p = patch + (y * PATCH + lane) * CPAD;
            #pragma unroll
            for (int c = 0; c < GROUP; ++c)
                p[c] = __ldg(g + c * HW);
        }
    }
    __syncthreads();

    // ---- compute: 2 outputs per warp (half-warps), lane = half*16 + channel ----
    int half = lane >> 4;
    int ch   = lane & 15;
    const float* plane = patch + ch;
    for (int p = w; p < 25; p += 8) {
        int o  = 2 * p + half;
        int oc = min(o, 48);
        int ph = oc / 7;
        int pw = oc - ph * 7;
        float4 ya = ytab[2 * ph], yb = ytab[2 * ph + 1];
        float4 xa = xtab[2 * pw], xb = xtab[2 * pw + 1];
        float acc = 0.0f;
        #pragma unroll
        for (int sy = 0; sy < 2; ++sy) {
            float4 ye = sy ? yb : ya;
            int rl = __float_as_int(ye.x);
            int rh = __float_as_int(ye.y);
            #pragma unroll
            for (int sx = 0; sx < 2; ++sx) {
                float4 xe = sx ? xb : xa;
                int cl = __float_as_int(xe.x);
                int chh = __float_as_int(xe.y);
                float tll = plane[rl + cl];
                float tlh = plane[rl + chh];
                float thl = plane[rh + cl];
                float thh = plane[rh + chh];
                float tlo = xe.z * tll + xe.w * tlh;
                float thi = xe.z * thl + xe.w * thh;
                acc += ye.z * tlo + ye.w * thi;
            }
        }
        if (o < 49)
            outbuf[o * CPAD + ch] = acc * 0.25f;
    }
    __syncthreads();

    // ---- coalesced writeback (stride-17 LDS: conflict-free) ----
    float* obase = out + ((size_t)k * CC + c0) * 49;
    for (int e = tid; e < GROUP * 49; e += 256) {
        int c = e / 49;
        int o = e - c * 49;
        obase[c * 49 + o] = outbuf[o * CPAD + c];
    }
}

extern "C" void kernel_launch(void* const* d_in, const int* in_sizes, int n_in,
                              void* d_out, int out_size)
{
    const float* feat = (const float*)d_in[0];
    const float* rois = (const float*)d_in[1];
    float*       out  = (float*)d_out;

    cudaFuncSetAttribute(roi_align_v4,
                         cudaFuncAttributeMaxDynamicSharedMemorySize, SMEM_BYTES);

    int n_rois = in_sizes[1] / 5;   // 1024
    roi_align_v4<<<n_rois * 16, 256, SMEM_BYTES>>>(feat, rois, out);
}

// round 14
// speedup vs baseline: 1.6814x; 1.6814x over previous
#include <cuda_runtime.h>

// RoIAlign2D: features (4,256,96,96) f32, rois (1024,5) f32 -> out (1024,256,7,7) f32
// OUT_SIZE=7, SPATIAL_SCALE=0.0625, SAMPLE_NUM=2
//
// v5b: Block = (roi, 32-channel group, y-half). Half 0 -> output rows 0..3,
// half 1 -> rows 4..6. Per-half y-span <= 12 rows -> patch smem ~31.6KB ->
// 6 blocks/SM (~72% occ) with GROUP=32 and full-warp 1-phase tap LDS.
// Patch layout [c][y][x], plane stride 253 (odd -> lane=channel is a bank
// permutation). FIX vs v5: outbuf channel stride 33 (was 29 < GROUP=32,
// causing cross-output aliasing).

#define CC     256
#define HH     96
#define WW     96
#define SCALE  0.0625f
#define PX     21          // max x span
#define PY     12          // max y span per half
#define PSIZE  253         // >= PY*PX = 252, odd
#define GROUP  32
#define HW     (HH * WW)
#define NOUTMX 28          // max outputs per block (4 rows * 7)
#define CPADO  33          // outbuf channel stride: >= GROUP, odd

#define PATCH_ELEMS  (GROUP * PSIZE)            // 8096
#define OUTBUF_ELEMS (NOUTMX * CPADO)           // 924
#define TAB_FLOATS   (22 * 4)                   // 8 y + 14 x float4 entries
#define SMEM_BYTES   ((TAB_FLOATS + PATCH_ELEMS + OUTBUF_ELEMS) * 4)  // 36432

__global__ __launch_bounds__(256) void roi_align_v5b(
    const float* __restrict__ feat,
    const float* __restrict__ rois,
    float* __restrict__ out)
{
    extern __shared__ float smem[];
    float4* ytab   = (float4*)smem;             // [8]  (this half's y samples)
    float4* xtab   = (float4*)smem + 8;         // [14]
    float*  patch  = smem + TAB_FLOATS;         // [GROUP][PSIZE]
    float*  outbuf = patch + PATCH_ELEMS;       // [NOUTMX][CPADO]

    int blk = blockIdx.x;
    int k   = blk >> 4;                 // roi
    int g   = (blk >> 1) & 7;           // channel group
    int h   = blk & 1;                  // y-half
    int c0  = g * GROUP;

    int phbase = h ? 4 : 0;
    int nrows  = h ? 3 : 4;
    int nout   = nrows * 7;             // 21 or 28
    int s0     = h ? 8 : 0;             // first y-sample index of this half
    int ny     = 2 * nrows;             // y samples in this half

    const float* r = rois + k * 5;
    int   b  = (int)__ldg(r);
    float x1 = __ldg(r + 1) * SCALE;
    float y1 = __ldg(r + 2) * SCALE;
    float x2 = __ldg(r + 3) * SCALE;
    float y2 = __ldg(r + 4) * SCALE;

    float bw = fmaxf(x2 - x1, 1.0f) * (1.0f / 7.0f);
    float bh = fmaxf(y2 - y1, 1.0f) * (1.0f / 7.0f);

    // Patch bounds: monotone clipped coords -> first/last sample bound all taps,
    // and clipping keeps everything in-bounds (no clamping needed when staging).
    float xcf = fminf(fmaxf(x1 + bw * 0.25f, 0.0f), (float)(WW - 1));
    int   x0  = (int)floorf(xcf);
    float xce = fminf(fmaxf(x1 + bw * 6.75f, 0.0f), (float)(WW - 1));
    int xspan = min((int)floorf(xce) + 1, WW - 1) - x0 + 1;          // <= 21

    float yoff0 = 0.25f + 0.5f * (float)s0;
    float yoffE = 0.25f + 0.5f * (float)(s0 + ny - 1);
    float ycf = fminf(fmaxf(y1 + bh * yoff0, 0.0f), (float)(HH - 1));
    int   y0  = (int)floorf(ycf);
    float yce = fminf(fmaxf(y1 + bh * yoffE, 0.0f), (float)(HH - 1));
    int yspan = min((int)floorf(yce) + 1, HH - 1) - y0 + 1;          // <= 12

    int tid  = threadIdx.x;
    int w    = tid >> 5;
    int lane = tid & 31;

    // ---- sample geometry tables: threads 0..ny-1 -> y, 8..21 -> x ----
    if (tid < 22 && (tid < ny || tid >= 8)) {
        bool  isY = tid < 8;
        int   s   = isY ? (s0 + tid) : (tid - 8);
        float start = isY ? y1 : x1;
        float bsz   = isY ? bh : bw;
        int   size  = isY ? HH : WW;
        int   org   = isY ? y0 : x0;
        int   mul   = isY ? PX : 1;

        float c  = start + bsz * (0.25f + 0.5f * (float)s);
        bool  v  = (c >= -1.0f) && (c <= (float)size);
        float cc = fminf(fmaxf(c, 0.0f), (float)(size - 1));
        float fl = floorf(cc);
        int   lo = (int)fl;
        int   hi = min(lo + 1, size - 1);
        float fr = cc - fl;
        float4 e;
        e.x = __int_as_float((lo - org) * mul);
        e.y = __int_as_float((hi - org) * mul);
        e.z = v ? (1.0f - fr) : 0.0f;
        e.w = v ? fr : 0.0f;
        if (isY) ytab[tid] = e; else xtab[tid - 8] = e;
    }

    // ---- stage patch: warp-per-row, lane = x, 32-channel inner loop ----
    // STS addr = c*PSIZE + y*PX + lane : lane-contiguous, conflict-free.
    const float* fbase = feat + (size_t)(b * CC + c0) * HW;
    for (int y = w; y < yspan; y += 8) {
        if (lane < xspan) {
            const float* gp = fbase + (y0 + y) * WW + x0 + lane;
            float*       pp = patch + y * PX + lane;
            #pragma unroll 8
            for (int c = 0; c < GROUP; ++c)
                pp[c * PSIZE] = __ldg(gp + c * HW);
        }
    }
    __syncthreads();

    // ---- compute: warp per output, lane = channel (stride-253 permutation) ----
    const float* plane = patch + lane * PSIZE;
    for (int o = w; o < nout; o += 8) {
        int ly = o / 7;                  // local output row
        int pw = o - ly * 7;
        float4 ya = ytab[2 * ly], yb = ytab[2 * ly + 1];
        float4 xa = xtab[2 * pw], xb = xtab[2 * pw + 1];
        float acc = 0.0f;
        #pragma unroll
        for (int sy = 0; sy < 2; ++sy) {
            float4 ye = sy ? yb : ya;
            int rl = __float_as_int(ye.x);
            int rh = __float_as_int(ye.y);
            #pragma unroll
            for (int sx = 0; sx < 2; ++sx) {
                float4 xe = sx ? xb : xa;
                int cl = __float_as_int(xe.x);
                int ch = __float_as_int(xe.y);
                float tll = plane[rl + cl];
                float tlh = plane[rl + ch];
                float thl = plane[rh + cl];
                float thh = plane[rh + ch];
                float tlo = xe.z * tll + xe.w * tlh;
                float thi = xe.z * thl + xe.w * thh;
                acc += ye.z * tlo + ye.w * thi;
            }
        }
        outbuf[o * CPADO + lane] = acc * 0.25f;
    }
    __syncthreads();

    // ---- coalesced writeback (stride-33 LDS: conflict-free) ----
    float* obase = out + ((size_t)k * CC + c0) * 49 + phbase * 7;
    for (int e = tid; e < GROUP * NOUTMX; e += 256) {
        int c = e / NOUTMX;
        int o = e - c * NOUTMX;
        if (o < nout)
            obase[c * 49 + o] = outbuf[o * CPADO + c];
    }
}

extern "C" void kernel_launch(void* const* d_in, const int* in_sizes, int n_in,
                              void* d_out, int out_size)
{
    const float* feat = (const float*)d_in[0];
    const float* rois = (const float*)d_in[1];
    float*       out  = (float*)d_out;

    cudaFuncSetAttribute(roi_align_v5b,
                         cudaFuncAttributeMaxDynamicSharedMemorySize, SMEM_BYTES);

    int n_rois = in_sizes[1] / 5;   // 1024
    roi_align_v5b<<<n_rois * 16, 256, SMEM_BYTES>>>(feat, rois, out);
}